// round 1
// baseline (speedup 1.0000x reference)
#include <cuda_runtime.h>
#include <cstdint>
#include <math.h>

#define T_DIM 4096
#define D_DIM 2048
#define H_NUM 16
#define HD_DIM 128
#define D3 (3 * D_DIM)
#define QK_SCALE 0.08838834764831845f   // 128^-0.5

// ---------------- scratch (device globals: no allocation allowed) ----------------
__device__ float g_qkv[(size_t)T_DIM * D3];    // (T, 3D)  ~100.7 MB
__device__ float g_att[(size_t)T_DIM * D_DIM]; // (T, D)   ~33.6 MB

// ---------------- generic fp32 SGEMM: C(MxN) = A(MxK) @ B(KxN), row-major ----------------
// BM=BN=128, BK=16, 256 threads, 8x8 microtile.
__global__ __launch_bounds__(256, 2) void sgemm_kernel(
    const float* __restrict__ A, const float* __restrict__ B, float* __restrict__ C,
    int M, int N, int K)
{
    __shared__ float As[16][128];
    __shared__ float Bs[16][128];

    const int bn = blockIdx.x * 128;
    const int bm = blockIdx.y * 128;
    const int tid = threadIdx.x;
    const int tx = tid & 15;
    const int ty = tid >> 4;

    // A loader: 128 rows x 16 cols; thread covers (arow, arow+64) x [acol..acol+3]
    const int arow = tid >> 2;
    const int acol = (tid & 3) * 4;
    // B loader: 16 rows x 128 cols; two float4 per thread
    const int brow = tid >> 4;
    const int bcol = (tid & 15) * 8;

    float acc[8][8];
#pragma unroll
    for (int i = 0; i < 8; i++)
#pragma unroll
        for (int j = 0; j < 8; j++) acc[i][j] = 0.f;

    for (int k0 = 0; k0 < K; k0 += 16) {
#pragma unroll
        for (int r = 0; r < 2; r++) {
            const float4 a = *(const float4*)(A + (size_t)(bm + arow + r * 64) * K + k0 + acol);
            As[acol + 0][arow + r * 64] = a.x;
            As[acol + 1][arow + r * 64] = a.y;
            As[acol + 2][arow + r * 64] = a.z;
            As[acol + 3][arow + r * 64] = a.w;
        }
#pragma unroll
        for (int c = 0; c < 2; c++) {
            *(float4*)&Bs[brow][bcol + c * 4] =
                *(const float4*)(B + (size_t)(k0 + brow) * N + bn + bcol + c * 4);
        }
        __syncthreads();

#pragma unroll
        for (int kk = 0; kk < 16; kk++) {
            float ar[8], br[8];
            *(float4*)(ar)     = *(const float4*)&As[kk][ty * 8];
            *(float4*)(ar + 4) = *(const float4*)&As[kk][ty * 8 + 4];
            *(float4*)(br)     = *(const float4*)&Bs[kk][tx * 8];
            *(float4*)(br + 4) = *(const float4*)&Bs[kk][tx * 8 + 4];
#pragma unroll
            for (int i = 0; i < 8; i++)
#pragma unroll
                for (int j = 0; j < 8; j++) acc[i][j] += ar[i] * br[j];
        }
        __syncthreads();
    }

#pragma unroll
    for (int i = 0; i < 8; i++) {
        float* cp = C + (size_t)(bm + ty * 8 + i) * N + bn + tx * 8;
        float4 o1 = make_float4(acc[i][0], acc[i][1], acc[i][2], acc[i][3]);
        float4 o2 = make_float4(acc[i][4], acc[i][5], acc[i][6], acc[i][7]);
        *(float4*)cp = o1;
        *(float4*)(cp + 4) = o2;
    }
}

// ---------------- L2-normalize q and k per (t, h) row of 128; fold QK_SCALE into q ----------------
__global__ __launch_bounds__(256) void l2norm_kernel(float* __restrict__ qkv)
{
    const int gw = (blockIdx.x * 256 + threadIdx.x) >> 5;   // global warp id
    const int lane = threadIdx.x & 31;
    // gw in [0, T*H*2)
    const int which = gw & 1;        // 0 = q, 1 = k
    const int th = gw >> 1;
    const int t = th >> 4;           // / H
    const int h = th & 15;           // % H
    float* row = qkv + (size_t)t * D3 + which * D_DIM + h * HD_DIM;

    float4 v = *(const float4*)(row + lane * 4);
    float s = v.x * v.x + v.y * v.y + v.z * v.z + v.w * v.w;
#pragma unroll
    for (int o = 16; o > 0; o >>= 1) s += __shfl_xor_sync(0xffffffffu, s, o);
    const float norm = sqrtf(s);
    float inv = 1.0f / fmaxf(norm, 1e-12f);
    if (which == 0) inv *= QK_SCALE;
    v.x *= inv; v.y *= inv; v.z *= inv; v.w *= inv;
    *(float4*)(row + lane * 4) = v;
}

// ---------------- flash attention (fp32, online softmax) ----------------
// Block: 64 queries of one head. Loop over key tiles of 64. 256 threads (tx 0..15, ty 0..15).
// Scores: 4x4 microtile. O accumulator: 4 rows x 8 cols.
#define FQS 68          // padded stride for [dim][token] transposed tiles
#define FPS 68          // padded stride for P
#define FLASH_SMEM ((128 * FQS * 2 + 64 * 128 + 64 * FPS + 64 * 3 + 64 * 17) * 4)

__global__ __launch_bounds__(256, 1) void flash_kernel(
    const float* __restrict__ qkv, const float* __restrict__ mask, float* __restrict__ out)
{
    extern __shared__ float smem[];
    float* sQt    = smem;                 // [128][FQS]
    float* sKt    = sQt + 128 * FQS;      // [128][FQS]
    float* sV     = sKt + 128 * FQS;      // [64][128]
    float* sP     = sV + 64 * 128;        // [64][FPS]
    float* sMax   = sP + 64 * FPS;        // [64]
    float* sSum   = sMax + 64;            // [64]
    float* sAlpha = sSum + 64;            // [64]
    float* sRed   = sAlpha + 64;          // [64][17]

    const int h  = blockIdx.y;
    const int q0 = blockIdx.x * 64;
    const int tid = threadIdx.x;
    const int tx = tid & 15;
    const int ty = tid >> 4;
    const int lrow = tid >> 2;            // loader row 0..63
    const int lc4  = tid & 3;

    // load Q (normalized, scaled) transposed into sQt[dim][query]
    const float* qbase = qkv + (size_t)q0 * D3 + (size_t)h * HD_DIM;
#pragma unroll
    for (int c4 = lc4; c4 < 32; c4 += 4) {
        const float4 v = *(const float4*)(qbase + (size_t)lrow * D3 + c4 * 4);
        const int c = c4 * 4;
        sQt[(c + 0) * FQS + lrow] = v.x;
        sQt[(c + 1) * FQS + lrow] = v.y;
        sQt[(c + 2) * FQS + lrow] = v.z;
        sQt[(c + 3) * FQS + lrow] = v.w;
    }
    if (tid < 64) { sMax[tid] = -1e30f; sSum[tid] = 0.f; }

    float acc[4][8];
#pragma unroll
    for (int i = 0; i < 4; i++)
#pragma unroll
        for (int j = 0; j < 8; j++) acc[i][j] = 0.f;
    __syncthreads();

    for (int k0 = 0; k0 < T_DIM; k0 += 64) {
        // load K transposed + V natural
        const float* kbase = qkv + (size_t)k0 * D3 + D_DIM + (size_t)h * HD_DIM;
        const float* vbase = kbase + D_DIM;
#pragma unroll
        for (int c4 = lc4; c4 < 32; c4 += 4) {
            const float4 kv = *(const float4*)(kbase + (size_t)lrow * D3 + c4 * 4);
            const int c = c4 * 4;
            sKt[(c + 0) * FQS + lrow] = kv.x;
            sKt[(c + 1) * FQS + lrow] = kv.y;
            sKt[(c + 2) * FQS + lrow] = kv.z;
            sKt[(c + 3) * FQS + lrow] = kv.w;
            *(float4*)(sV + lrow * 128 + c4 * 4) =
                *(const float4*)(vbase + (size_t)lrow * D3 + c4 * 4);
        }
        __syncthreads();

        // scores: rows ty*4.., cols tx*4..
        float sc[4][4];
#pragma unroll
        for (int i = 0; i < 4; i++)
#pragma unroll
            for (int j = 0; j < 4; j++) sc[i][j] = 0.f;

#pragma unroll 8
        for (int kk = 0; kk < 128; kk++) {
            const float4 q4 = *(const float4*)(sQt + kk * FQS + ty * 4);
            const float4 k4 = *(const float4*)(sKt + kk * FQS + tx * 4);
            const float qa[4] = {q4.x, q4.y, q4.z, q4.w};
            const float ka[4] = {k4.x, k4.y, k4.z, k4.w};
#pragma unroll
            for (int i = 0; i < 4; i++)
#pragma unroll
                for (int j = 0; j < 4; j++) sc[i][j] += qa[i] * ka[j];
        }

        // mask + per-thread row max
#pragma unroll
        for (int i = 0; i < 4; i++) {
            const float4 mv = *(const float4*)(mask + (size_t)(q0 + ty * 4 + i) * T_DIM + k0 + tx * 4);
            sc[i][0] += mv.x; sc[i][1] += mv.y; sc[i][2] += mv.z; sc[i][3] += mv.w;
            const float m = fmaxf(fmaxf(sc[i][0], sc[i][1]), fmaxf(sc[i][2], sc[i][3]));
            sRed[(ty * 4 + i) * 17 + tx] = m;
        }
        __syncthreads();

        if (tid < 64) {
            float tm = -1e30f;
#pragma unroll
            for (int x = 0; x < 16; x++) tm = fmaxf(tm, sRed[tid * 17 + x]);
            const float mold = sMax[tid];
            const float mnew = fmaxf(mold, tm);
            sAlpha[tid] = __expf(mold - mnew);
            sMax[tid] = mnew;
        }
        __syncthreads();

        // exp, write P, row partial sums
#pragma unroll
        for (int i = 0; i < 4; i++) {
            const float mi = sMax[ty * 4 + i];
            float rs = 0.f;
#pragma unroll
            for (int j = 0; j < 4; j++) {
                const float p = __expf(sc[i][j] - mi);
                sc[i][j] = p;
                rs += p;
            }
            *(float4*)(sP + (ty * 4 + i) * FPS + tx * 4) =
                make_float4(sc[i][0], sc[i][1], sc[i][2], sc[i][3]);
            sRed[(ty * 4 + i) * 17 + tx] = rs;
        }
        __syncthreads();

        if (tid < 64) {
            float s = 0.f;
#pragma unroll
            for (int x = 0; x < 16; x++) s += sRed[tid * 17 + x];
            sSum[tid] = sSum[tid] * sAlpha[tid] + s;
        }

        // rescale accumulator
#pragma unroll
        for (int i = 0; i < 4; i++) {
            const float a = sAlpha[ty * 4 + i];
#pragma unroll
            for (int j = 0; j < 8; j++) acc[i][j] *= a;
        }

        // O += P @ V   (O rows ty*4.., cols tx*8..)
#pragma unroll 4
        for (int kk0 = 0; kk0 < 64; kk0 += 4) {
            float pa[4][4];
#pragma unroll
            for (int i = 0; i < 4; i++) {
                const float4 pv = *(const float4*)(sP + (ty * 4 + i) * FPS + kk0);
                pa[i][0] = pv.x; pa[i][1] = pv.y; pa[i][2] = pv.z; pa[i][3] = pv.w;
            }
#pragma unroll
            for (int u = 0; u < 4; u++) {
                const int kk = kk0 + u;
                const float4 va = *(const float4*)(sV + kk * 128 + tx * 8);
                const float4 vb = *(const float4*)(sV + kk * 128 + tx * 8 + 4);
                const float vv[8] = {va.x, va.y, va.z, va.w, vb.x, vb.y, vb.z, vb.w};
#pragma unroll
                for (int i = 0; i < 4; i++)
#pragma unroll
                    for (int j = 0; j < 8; j++) acc[i][j] += pa[i][u] * vv[j];
            }
        }
        __syncthreads();
    }

    // epilogue: divide by l, write to attention-output buffer (T, D)
#pragma unroll
    for (int i = 0; i < 4; i++) {
        const float inv = 1.0f / sSum[ty * 4 + i];
        float* op = out + (size_t)(q0 + ty * 4 + i) * D_DIM + h * HD_DIM + tx * 8;
        *(float4*)op       = make_float4(acc[i][0] * inv, acc[i][1] * inv, acc[i][2] * inv, acc[i][3] * inv);
        *(float4*)(op + 4) = make_float4(acc[i][4] * inv, acc[i][5] * inv, acc[i][6] * inv, acc[i][7] * inv);
    }
}

// ---------------- launch ----------------
extern "C" void kernel_launch(void* const* d_in, const int* in_sizes, int n_in,
                              void* d_out, int out_size)
{
    const float* x    = (const float*)d_in[0];
    const float* mask = (const float*)d_in[1];
    const float* Wqkv = (const float*)d_in[2];
    const float* Wout = (const float*)d_in[3];
    float* out = (float*)d_out;

    float* qkv = nullptr;
    float* att = nullptr;
    cudaGetSymbolAddress((void**)&qkv, g_qkv);
    cudaGetSymbolAddress((void**)&att, g_att);

    // 1) qkv = x @ W_qkv
    sgemm_kernel<<<dim3(D3 / 128, T_DIM / 128), 256>>>(x, Wqkv, qkv, T_DIM, D3, D_DIM);

    // 2) l2-normalize q,k per (t,h); fold softmax scale into q
    l2norm_kernel<<<(T_DIM * H_NUM * 2) / 8, 256>>>(qkv);

    // 3) flash attention -> g_att (T, D)
    cudaFuncSetAttribute(flash_kernel, cudaFuncAttributeMaxDynamicSharedMemorySize, FLASH_SMEM);
    flash_kernel<<<dim3(T_DIM / 64, H_NUM), 256, FLASH_SMEM>>>(qkv, mask, att);

    // 4) out = att @ W_out
    sgemm_kernel<<<dim3(D_DIM / 128, T_DIM / 128), 256>>>(att, Wout, out, T_DIM, D_DIM, D_DIM);
}

// round 5
// speedup vs baseline: 1.3428x; 1.3428x over previous
#include <cuda_runtime.h>
#include <cstdint>
#include <math.h>

#define T_DIM 4096
#define D_DIM 2048
#define H_NUM 16
#define HD_DIM 128
#define D3 (3 * D_DIM)
#define QK_SCALE 0.08838834764831845f   // 128^-0.5

// ---------------- scratch (device globals: no allocation allowed) ----------------
__device__ float g_qkv[(size_t)T_DIM * D3];    // (T, 3D)  ~100.7 MB
__device__ float g_att[(size_t)T_DIM * D_DIM]; // (T, D)   ~33.6 MB

__device__ __forceinline__ uint32_t f2tf32(float x) {
    uint32_t u;
    asm("cvt.rna.tf32.f32 %0, %1;" : "=r"(u) : "f"(x));
    return u;
}

__device__ __forceinline__ void mma_tf32(float* c, const uint32_t* a, const uint32_t* b) {
    asm volatile(
        "mma.sync.aligned.m16n8k8.row.col.f32.tf32.tf32.f32 "
        "{%0,%1,%2,%3}, {%4,%5,%6,%7}, {%8,%9}, {%0,%1,%2,%3};"
        : "+f"(c[0]), "+f"(c[1]), "+f"(c[2]), "+f"(c[3])
        : "r"(a[0]), "r"(a[1]), "r"(a[2]), "r"(a[3]), "r"(b[0]), "r"(b[1]));
}

// ================= tf32 mma.sync GEMM: C(MxN) = A(MxK) @ B(KxN), row-major fp32 =========
// BM=BN=128, BK=32, 256 threads (8 warps, 2x4), warp tile 64x32, frag grid 4x4.
#define ASTR 36      // As[m][k] padded stride  -> fragment banks (m*4+k)%32 all distinct
#define BSTR 136     // Bs[k][n] padded stride  -> fragment banks (k*8+n)%32 all distinct

__global__ __launch_bounds__(256) void tc_gemm(
    const float* __restrict__ A, const float* __restrict__ B, float* __restrict__ C,
    int M, int N, int K)
{
    __shared__ uint32_t As[128 * ASTR];   // 18.0 KB
    __shared__ uint32_t Bs[32 * BSTR];    // 17.0 KB

    const int tid  = threadIdx.x;
    const int wid  = tid >> 5;
    const int lane = tid & 31;
    const int g    = lane >> 2;   // group id (0..7)
    const int t    = lane & 3;    // thread in group (0..3)

    const int bn = blockIdx.x * 128;
    const int bm = blockIdx.y * 128;
    const int wm = (wid >> 2) * 64;   // warp row base within tile
    const int wn = (wid & 3) * 32;    // warp col base within tile

    // loaders
    const int a_row = tid >> 3, a_q = tid & 7;      // A: 32 rows x 8 quads per iter, 4 iters
    const int b_row = tid >> 5, b_q = tid & 31;     // B: 8 rows x 32 quads per iter, 4 iters

    float acc[4][4][4];
#pragma unroll
    for (int i = 0; i < 4; i++)
#pragma unroll
        for (int j = 0; j < 4; j++)
#pragma unroll
            for (int r = 0; r < 4; r++) acc[i][j][r] = 0.f;

    float4 pa[4], pb[4];

    // prefetch chunk 0
#pragma unroll
    for (int r = 0; r < 4; r++)
        pa[r] = *(const float4*)(A + (size_t)(bm + a_row + r * 32) * K + a_q * 4);
#pragma unroll
    for (int r = 0; r < 4; r++)
        pb[r] = *(const float4*)(B + (size_t)(b_row + r * 8) * N + bn + b_q * 4);

    const int nch = K >> 5;
    for (int ch = 0; ch < nch; ch++) {
        // store prefetched chunk into smem (convert to tf32)
#pragma unroll
        for (int r = 0; r < 4; r++) {
            uint32_t* p = As + (a_row + r * 32) * ASTR + a_q * 4;
            p[0] = f2tf32(pa[r].x); p[1] = f2tf32(pa[r].y);
            p[2] = f2tf32(pa[r].z); p[3] = f2tf32(pa[r].w);
        }
#pragma unroll
        for (int r = 0; r < 4; r++) {
            uint32_t* p = Bs + (b_row + r * 8) * BSTR + b_q * 4;
            p[0] = f2tf32(pb[r].x); p[1] = f2tf32(pb[r].y);
            p[2] = f2tf32(pb[r].z); p[3] = f2tf32(pb[r].w);
        }
        __syncthreads();

        // prefetch next chunk while doing MMA on this one
        if (ch + 1 < nch) {
            const int k0 = (ch + 1) << 5;
#pragma unroll
            for (int r = 0; r < 4; r++)
                pa[r] = *(const float4*)(A + (size_t)(bm + a_row + r * 32) * K + k0 + a_q * 4);
#pragma unroll
            for (int r = 0; r < 4; r++)
                pb[r] = *(const float4*)(B + (size_t)(k0 + b_row + r * 8) * N + bn + b_q * 4);
        }

#pragma unroll
        for (int ks = 0; ks < 4; ks++) {
            const int kk = ks * 8;
            uint32_t af[4][4], bf[4][2];
#pragma unroll
            for (int mi = 0; mi < 4; mi++) {
                const uint32_t* base = As + (wm + mi * 16 + g) * ASTR + kk + t;
                af[mi][0] = base[0];
                af[mi][1] = base[8 * ASTR];
                af[mi][2] = base[4];
                af[mi][3] = base[8 * ASTR + 4];
            }
#pragma unroll
            for (int ni = 0; ni < 4; ni++) {
                const uint32_t* base = Bs + (kk + t) * BSTR + wn + ni * 8 + g;
                bf[ni][0] = base[0];
                bf[ni][1] = base[4 * BSTR];
            }
#pragma unroll
            for (int mi = 0; mi < 4; mi++)
#pragma unroll
                for (int ni = 0; ni < 4; ni++)
                    mma_tf32(acc[mi][ni], af[mi], bf[ni]);
        }
        __syncthreads();
    }

    // epilogue: direct global stores (float2 per fragment half)
#pragma unroll
    for (int mi = 0; mi < 4; mi++) {
#pragma unroll
        for (int ni = 0; ni < 4; ni++) {
            const int row = bm + wm + mi * 16 + g;
            const int col = bn + wn + ni * 8 + t * 2;
            *(float2*)(C + (size_t)row * N + col)       = make_float2(acc[mi][ni][0], acc[mi][ni][1]);
            *(float2*)(C + (size_t)(row + 8) * N + col) = make_float2(acc[mi][ni][2], acc[mi][ni][3]);
        }
    }
}

// ---------------- L2-normalize q and k per (t, h) row of 128; fold QK_SCALE into q ----------------
__global__ __launch_bounds__(256) void l2norm_kernel(float* __restrict__ qkv)
{
    const int gw = (blockIdx.x * 256 + threadIdx.x) >> 5;
    const int lane = threadIdx.x & 31;
    const int which = gw & 1;        // 0 = q, 1 = k
    const int th = gw >> 1;
    const int t = th >> 4;
    const int h = th & 15;
    float* row = qkv + (size_t)t * D3 + which * D_DIM + h * HD_DIM;

    float4 v = *(const float4*)(row + lane * 4);
    float s = v.x * v.x + v.y * v.y + v.z * v.z + v.w * v.w;
#pragma unroll
    for (int o = 16; o > 0; o >>= 1) s += __shfl_xor_sync(0xffffffffu, s, o);
    const float norm = sqrtf(s);
    float inv = 1.0f / fmaxf(norm, 1e-12f);
    if (which == 0) inv *= QK_SCALE;
    v.x *= inv; v.y *= inv; v.z *= inv; v.w *= inv;
    *(float4*)(row + lane * 4) = v;
}

// ---------------- flash attention (fp32, online softmax) ----------------
#define FQS 68
#define FPS 68
#define FLASH_SMEM ((128 * FQS * 2 + 64 * 128 + 64 * FPS + 64 * 3 + 64 * 17) * 4)

__global__ __launch_bounds__(256, 1) void flash_kernel(
    const float* __restrict__ qkv, const float* __restrict__ mask, float* __restrict__ out)
{
    extern __shared__ float smem[];
    float* sQt    = smem;
    float* sKt    = sQt + 128 * FQS;
    float* sV     = sKt + 128 * FQS;
    float* sP     = sV + 64 * 128;
    float* sMax   = sP + 64 * FPS;
    float* sSum   = sMax + 64;
    float* sAlpha = sSum + 64;
    float* sRed   = sAlpha + 64;

    const int h  = blockIdx.y;
    const int q0 = blockIdx.x * 64;
    const int tid = threadIdx.x;
    const int tx = tid & 15;
    const int ty = tid >> 4;
    const int lrow = tid >> 2;
    const int lc4  = tid & 3;

    const float* qbase = qkv + (size_t)q0 * D3 + (size_t)h * HD_DIM;
#pragma unroll
    for (int c4 = lc4; c4 < 32; c4 += 4) {
        const float4 v = *(const float4*)(qbase + (size_t)lrow * D3 + c4 * 4);
        const int c = c4 * 4;
        sQt[(c + 0) * FQS + lrow] = v.x;
        sQt[(c + 1) * FQS + lrow] = v.y;
        sQt[(c + 2) * FQS + lrow] = v.z;
        sQt[(c + 3) * FQS + lrow] = v.w;
    }
    if (tid < 64) { sMax[tid] = -1e30f; sSum[tid] = 0.f; }

    float acc[4][8];
#pragma unroll
    for (int i = 0; i < 4; i++)
#pragma unroll
        for (int j = 0; j < 8; j++) acc[i][j] = 0.f;
    __syncthreads();

    for (int k0 = 0; k0 < T_DIM; k0 += 64) {
        const float* kbase = qkv + (size_t)k0 * D3 + D_DIM + (size_t)h * HD_DIM;
        const float* vbase = kbase + D_DIM;
#pragma unroll
        for (int c4 = lc4; c4 < 32; c4 += 4) {
            const float4 kv = *(const float4*)(kbase + (size_t)lrow * D3 + c4 * 4);
            const int c = c4 * 4;
            sKt[(c + 0) * FQS + lrow] = kv.x;
            sKt[(c + 1) * FQS + lrow] = kv.y;
            sKt[(c + 2) * FQS + lrow] = kv.z;
            sKt[(c + 3) * FQS + lrow] = kv.w;
            *(float4*)(sV + lrow * 128 + c4 * 4) =
                *(const float4*)(vbase + (size_t)lrow * D3 + c4 * 4);
        }
        __syncthreads();

        float sc[4][4];
#pragma unroll
        for (int i = 0; i < 4; i++)
#pragma unroll
            for (int j = 0; j < 4; j++) sc[i][j] = 0.f;

#pragma unroll 8
        for (int kk = 0; kk < 128; kk++) {
            const float4 q4 = *(const float4*)(sQt + kk * FQS + ty * 4);
            const float4 k4 = *(const float4*)(sKt + kk * FQS + tx * 4);
            const float qa[4] = {q4.x, q4.y, q4.z, q4.w};
            const float ka[4] = {k4.x, k4.y, k4.z, k4.w};
#pragma unroll
            for (int i = 0; i < 4; i++)
#pragma unroll
                for (int j = 0; j < 4; j++) sc[i][j] += qa[i] * ka[j];
        }

#pragma unroll
        for (int i = 0; i < 4; i++) {
            const float4 mv = *(const float4*)(mask + (size_t)(q0 + ty * 4 + i) * T_DIM + k0 + tx * 4);
            sc[i][0] += mv.x; sc[i][1] += mv.y; sc[i][2] += mv.z; sc[i][3] += mv.w;
            const float m = fmaxf(fmaxf(sc[i][0], sc[i][1]), fmaxf(sc[i][2], sc[i][3]));
            sRed[(ty * 4 + i) * 17 + tx] = m;
        }
        __syncthreads();

        if (tid < 64) {
            float tm = -1e30f;
#pragma unroll
            for (int x = 0; x < 16; x++) tm = fmaxf(tm, sRed[tid * 17 + x]);
            const float mold = sMax[tid];
            const float mnew = fmaxf(mold, tm);
            sAlpha[tid] = __expf(mold - mnew);
            sMax[tid] = mnew;
        }
        __syncthreads();

#pragma unroll
        for (int i = 0; i < 4; i++) {
            const float mi = sMax[ty * 4 + i];
            float rs = 0.f;
#pragma unroll
            for (int j = 0; j < 4; j++) {
                const float p = __expf(sc[i][j] - mi);
                sc[i][j] = p;
                rs += p;
            }
            *(float4*)(sP + (ty * 4 + i) * FPS + tx * 4) =
                make_float4(sc[i][0], sc[i][1], sc[i][2], sc[i][3]);
            sRed[(ty * 4 + i) * 17 + tx] = rs;
        }
        __syncthreads();

        if (tid < 64) {
            float s = 0.f;
#pragma unroll
            for (int x = 0; x < 16; x++) s += sRed[tid * 17 + x];
            sSum[tid] = sSum[tid] * sAlpha[tid] + s;
        }

#pragma unroll
        for (int i = 0; i < 4; i++) {
            const float a = sAlpha[ty * 4 + i];
#pragma unroll
            for (int j = 0; j < 8; j++) acc[i][j] *= a;
        }

#pragma unroll 4
        for (int kk0 = 0; kk0 < 64; kk0 += 4) {
            float pa[4][4];
#pragma unroll
            for (int i = 0; i < 4; i++) {
                const float4 pv = *(const float4*)(sP + (ty * 4 + i) * FPS + kk0);
                pa[i][0] = pv.x; pa[i][1] = pv.y; pa[i][2] = pv.z; pa[i][3] = pv.w;
            }
#pragma unroll
            for (int u = 0; u < 4; u++) {
                const int kk = kk0 + u;
                const float4 va = *(const float4*)(sV + kk * 128 + tx * 8);
                const float4 vb = *(const float4*)(sV + kk * 128 + tx * 8 + 4);
                const float vv[8] = {va.x, va.y, va.z, va.w, vb.x, vb.y, vb.z, vb.w};
#pragma unroll
                for (int i = 0; i < 4; i++)
#pragma unroll
                    for (int j = 0; j < 8; j++) acc[i][j] += pa[i][u] * vv[j];
            }
        }
        __syncthreads();
    }

#pragma unroll
    for (int i = 0; i < 4; i++) {
        const float inv = 1.0f / sSum[ty * 4 + i];
        float* op = out + (size_t)(q0 + ty * 4 + i) * D_DIM + h * HD_DIM + tx * 8;
        *(float4*)op       = make_float4(acc[i][0] * inv, acc[i][1] * inv, acc[i][2] * inv, acc[i][3] * inv);
        *(float4*)(op + 4) = make_float4(acc[i][4] * inv, acc[i][5] * inv, acc[i][6] * inv, acc[i][7] * inv);
    }
}

// ---------------- launch ----------------
extern "C" void kernel_launch(void* const* d_in, const int* in_sizes, int n_in,
                              void* d_out, int out_size)
{
    const float* x    = (const float*)d_in[0];
    const float* mask = (const float*)d_in[1];
    const float* Wqkv = (const float*)d_in[2];
    const float* Wout = (const float*)d_in[3];
    float* out = (float*)d_out;

    float* qkv = nullptr;
    float* att = nullptr;
    cudaGetSymbolAddress((void**)&qkv, g_qkv);
    cudaGetSymbolAddress((void**)&att, g_att);

    // 1) qkv = x @ W_qkv   (tf32 mma.sync)
    tc_gemm<<<dim3(D3 / 128, T_DIM / 128), 256>>>(x, Wqkv, qkv, T_DIM, D3, D_DIM);

    // 2) l2-normalize q,k per (t,h); fold softmax scale into q
    l2norm_kernel<<<(T_DIM * H_NUM * 2) / 8, 256>>>(qkv);

    // 3) flash attention -> g_att (T, D)
    cudaFuncSetAttribute(flash_kernel, cudaFuncAttributeMaxDynamicSharedMemorySize, FLASH_SMEM);
    flash_kernel<<<dim3(T_DIM / 64, H_NUM), 256, FLASH_SMEM>>>(qkv, mask, att);

    // 4) out = att @ W_out   (tf32 mma.sync)
    tc_gemm<<<dim3(D_DIM / 128, T_DIM / 128), 256>>>(att, Wout, out, T_DIM, D_DIM, D_DIM);
}